// round 16
// baseline (speedup 1.0000x reference)
#include <cuda_runtime.h>
#include <cuda_bf16.h>
#include <cstdint>

#define BATCH 64
#define SEQ   320
#define CH    768
#define HEADS 12
#define HDIM  64
#define KDIM  768
#define MROWS (BATCH*SEQ)   // 20480

// ---------------- device global scratch (allocation-free rule) --------------
__device__ __nv_bfloat16 g_qh[(size_t)BATCH*HEADS*SEQ*HDIM];
__device__ __nv_bfloat16 g_ql[(size_t)BATCH*HEADS*SEQ*HDIM];
__device__ __nv_bfloat16 g_kh[(size_t)BATCH*HEADS*SEQ*HDIM];
__device__ __nv_bfloat16 g_kl[(size_t)BATCH*HEADS*SEQ*HDIM];
__device__ __nv_bfloat16 g_vh[(size_t)BATCH*HEADS*SEQ*HDIM];
__device__ __nv_bfloat16 g_vl[(size_t)BATCH*HEADS*SEQ*HDIM];
__device__ __nv_bfloat16 g_xhi[(size_t)MROWS*KDIM];
__device__ __nv_bfloat16 g_xlo[(size_t)MROWS*KDIM];
__device__ __nv_bfloat16 g_wqkv_hi[(size_t)3*CH*KDIM];
__device__ __nv_bfloat16 g_wqkv_lo[(size_t)3*CH*KDIM];
__device__ __nv_bfloat16 g_wproj_hi[(size_t)CH*KDIM];
__device__ __nv_bfloat16 g_wproj_lo[(size_t)CH*KDIM];
__device__ __nv_bfloat16 g_att_hi[(size_t)MROWS*CH];
__device__ __nv_bfloat16 g_att_lo[(size_t)MROWS*CH];

// ---------------- helpers ---------------------------------------------------
__device__ __forceinline__ uint32_t smem_u32(const void* p) {
    uint32_t a;
    asm("{ .reg .u64 t; cvta.to.shared.u64 t, %1; cvt.u32.u64 %0, t; }"
        : "=r"(a) : "l"(p));
    return a;
}
__device__ __forceinline__ void ldmx4(uint32_t* r, uint32_t addr) {
    asm volatile("ldmatrix.sync.aligned.m8n8.x4.shared.b16 {%0,%1,%2,%3}, [%4];"
        : "=r"(r[0]), "=r"(r[1]), "=r"(r[2]), "=r"(r[3]) : "r"(addr));
}
__device__ __forceinline__ void ldmx4t(uint32_t* r, uint32_t addr) {
    asm volatile("ldmatrix.sync.aligned.m8n8.x4.trans.shared.b16 {%0,%1,%2,%3}, [%4];"
        : "=r"(r[0]), "=r"(r[1]), "=r"(r[2]), "=r"(r[3]) : "r"(addr));
}
__device__ __forceinline__ void mma16816(float* c, const uint32_t* a,
                                         uint32_t b0, uint32_t b1) {
    asm volatile("mma.sync.aligned.m16n8k16.row.col.f32.bf16.bf16.f32 "
        "{%0,%1,%2,%3}, {%4,%5,%6,%7}, {%8,%9}, {%0,%1,%2,%3};"
        : "+f"(c[0]), "+f"(c[1]), "+f"(c[2]), "+f"(c[3])
        : "r"(a[0]), "r"(a[1]), "r"(a[2]), "r"(a[3]), "r"(b0), "r"(b1));
}
__device__ __forceinline__ uint32_t pack_bf2(__nv_bfloat16 a, __nv_bfloat16 b) {
    return ((uint32_t)__bfloat16_as_ushort(b) << 16) | (uint32_t)__bfloat16_as_ushort(a);
}
__device__ __forceinline__ void split2(float x, float y, uint32_t& hi, uint32_t& lo) {
    __nv_bfloat16 hx = __float2bfloat16(x), hy = __float2bfloat16(y);
    hi = pack_bf2(hx, hy);
    lo = pack_bf2(__float2bfloat16(x - __bfloat162float(hx)),
                  __float2bfloat16(y - __bfloat162float(hy)));
}

// ---------------- fp32 -> bf16 hi/lo split ----------------------------------
template<int T>
__global__ void cvt_split(const float* __restrict__ s, int n4) {
    __nv_bfloat16* hi = (T == 0) ? g_xhi : (T == 1) ? g_wqkv_hi : g_wproj_hi;
    __nv_bfloat16* lo = (T == 0) ? g_xlo : (T == 1) ? g_wqkv_lo : g_wproj_lo;
    int i = blockIdx.x * blockDim.x + threadIdx.x;
    if (i >= n4) return;
    float4 v = ((const float4*)s)[i];
    uint32_t h0, l0, h1, l1;
    split2(v.x, v.y, h0, l0);
    split2(v.z, v.w, h1, l1);
    ((uint2*)hi)[i] = make_uint2(h0, h1);
    ((uint2*)lo)[i] = make_uint2(l0, l1);
}

// ---------------------------------------------------------------------------
// bf16-split warp-MMA GEMM. 128x128 tile, 8 warps (4m x 2n), warp tile 32x64.
// BK=16, FOUR-stage cp.async pipeline (loads run 3 chunks ahead; wait_group 2
// with exact tail handling). Row stride 24 bf16 (48B): 16B-aligned for
// cp.async, rows map to distinct 16B banks mod 128 -> ldmatrix conflict-free.
// MODE 1: A=x(split), W=wqkv(split), epilogue splits to bf16 -> g_{q,k,v}{h,l}.
// MODE 0: A=att(split), W=wproj(split), out[m*CH+n] fp32.
// ---------------------------------------------------------------------------
#define RSTRIDE 24                   // bf16 units per row (16 + 8 pad) = 48 B
#define TILE_B  (128*RSTRIDE*2)      // 6144 B per 128x16 tile
#define STAGE_B (4*TILE_B)           // 24576 B  (Ah, Al, Bh, Bl)
#define NSTAGE  4
#define SMEM_DYN (NSTAGE*STAGE_B)    // 98304 B

template<int MODE>
__global__ void __launch_bounds__(256, 2)
gemm_mma(const float* __restrict__ bias, float* __restrict__ out)
{
    extern __shared__ char dsm[];
    __shared__ float sbias[128];

    const __nv_bfloat16* Ahi = (MODE == 1) ? g_xhi : g_att_hi;
    const __nv_bfloat16* Alo = (MODE == 1) ? g_xlo : g_att_lo;
    const __nv_bfloat16* Whi = (MODE == 1) ? g_wqkv_hi : g_wproj_hi;
    const __nv_bfloat16* Wlo = (MODE == 1) ? g_wqkv_lo : g_wproj_lo;

    const int tid = threadIdx.x;
    const int wid = tid >> 5, l = tid & 31;
    const int bx = blockIdx.x, by = blockIdx.y;
    const int warp_m = wid & 3, warp_n = wid >> 2;

    if (tid < 128) sbias[tid] = bias[bx * 128 + tid];

    const uint32_t sb0 = smem_u32(dsm);
    // loader: 128 rows x 16 bf16 per tile; each thread: 1 x 16B per tile
    const int lrow = tid >> 1, lseg = tid & 1;
    const __nv_bfloat16* srcs[4] = { Ahi, Alo, Whi, Wlo };
    const int rb_a = by * 128, rb_b = bx * 128;

    auto load_chunk = [&](int c) {
        const uint32_t sb = sb0 + (c & (NSTAGE - 1)) * STAGE_B;
        #pragma unroll
        for (int t = 0; t < 4; ++t) {
            const __nv_bfloat16* src = srcs[t];
            const int rowbase = (t < 2) ? rb_a : rb_b;
            const void* gp = src + (size_t)(rowbase + lrow) * KDIM + c * 16 + lseg * 8;
            uint32_t sp = sb + t * TILE_B + (lrow * RSTRIDE + lseg * 8) * 2;
            asm volatile("cp.async.cg.shared.global [%0], [%1], 16;"
                         :: "r"(sp), "l"(gp) : "memory");
        }
        asm volatile("cp.async.commit_group;" ::: "memory");
    };

    float acc[2][8][4];
    #pragma unroll
    for (int i = 0; i < 2; i++)
        #pragma unroll
        for (int j = 0; j < 8; j++)
            #pragma unroll
            for (int k = 0; k < 4; k++) acc[i][j][k] = 0.f;

    const int lm = l & 15, lkh = (l >> 4) * 8;
    const uint32_t a_off = ((warp_m * 32 + lm) * RSTRIDE + lkh) * 2;
    const uint32_t b_off = ((warp_n * 64 + lm) * RSTRIDE + lkh) * 2;

    load_chunk(0);
    load_chunk(1);
    load_chunk(2);

    const int NC = KDIM / 16;   // 48
    for (int c = 0; c < NC; ++c) {
        // wait for chunk c; keep up to 2 younger groups in flight
        if (c + 3 <= NC) {
            asm volatile("cp.async.wait_group 2;" ::: "memory");
        } else if (c + 2 == NC) {
            asm volatile("cp.async.wait_group 1;" ::: "memory");
        } else {
            asm volatile("cp.async.wait_group 0;" ::: "memory");
        }
        __syncthreads();   // publish chunk c; retire readers of buf (c+3)&3

        if (c + 3 < NC) load_chunk(c + 3);

        const uint32_t sb = sb0 + (c & (NSTAGE - 1)) * STAGE_B;
        uint32_t ah[2][4], al[2][4], bb[4][4];
        #pragma unroll
        for (int mf = 0; mf < 2; ++mf) {
            ldmx4(ah[mf], sb + a_off + mf * (16 * RSTRIDE * 2));
            ldmx4(al[mf], sb + TILE_B + a_off + mf * (16 * RSTRIDE * 2));
        }
        #pragma unroll
        for (int np = 0; np < 4; ++np)
            ldmx4(bb[np], sb + 2 * TILE_B + b_off + np * (16 * RSTRIDE * 2));
        #pragma unroll
        for (int mf = 0; mf < 2; ++mf)
            #pragma unroll
            for (int np = 0; np < 4; ++np) {
                mma16816(acc[mf][2*np],   ah[mf], bb[np][0], bb[np][2]);
                mma16816(acc[mf][2*np+1], ah[mf], bb[np][1], bb[np][3]);
            }
        #pragma unroll
        for (int mf = 0; mf < 2; ++mf)
            #pragma unroll
            for (int np = 0; np < 4; ++np) {
                mma16816(acc[mf][2*np],   al[mf], bb[np][0], bb[np][2]);
                mma16816(acc[mf][2*np+1], al[mf], bb[np][1], bb[np][3]);
            }
        #pragma unroll
        for (int np = 0; np < 4; ++np)
            ldmx4(bb[np], sb + 3 * TILE_B + b_off + np * (16 * RSTRIDE * 2));
        #pragma unroll
        for (int mf = 0; mf < 2; ++mf)
            #pragma unroll
            for (int np = 0; np < 4; ++np) {
                mma16816(acc[mf][2*np],   ah[mf], bb[np][0], bb[np][2]);
                mma16816(acc[mf][2*np+1], ah[mf], bb[np][1], bb[np][3]);
            }
    }

    const int qr = l >> 2, qc = (l & 3) * 2;
    #pragma unroll
    for (int mf = 0; mf < 2; ++mf) {
        #pragma unroll
        for (int nt = 0; nt < 8; ++nt) {
            const int col = warp_n * 64 + nt * 8 + qc;
            const float b0 = sbias[col], b1 = sbias[col + 1];
            #pragma unroll
            for (int half = 0; half < 2; ++half) {
                const int row = warp_m * 32 + mf * 16 + qr + half * 8;
                const float vx = acc[mf][nt][2*half] + b0;
                const float vy = acc[mf][nt][2*half+1] + b1;
                const int m = by * 128 + row;
                if (MODE == 0) {
                    *(float2*)(out + (size_t)m * CH + bx * 128 + col) =
                        make_float2(vx, vy);
                } else {
                    const int cg = bx * 128 + col;
                    const int which = cg / CH;
                    const int rem = cg - which * CH;
                    const int h = rem >> 6, d0 = rem & 63;
                    const int b = m / SEQ, n = m - b * SEQ;
                    __nv_bfloat16* dh = (which == 0) ? g_qh : (which == 1) ? g_kh : g_vh;
                    __nv_bfloat16* dl = (which == 0) ? g_ql : (which == 1) ? g_kl : g_vl;
                    const size_t off = ((size_t)(b * HEADS + h) * SEQ + n) * HDIM + d0;
                    uint32_t hi, lo;
                    split2(vx, vy, hi, lo);
                    *(uint32_t*)(dh + off) = hi;
                    *(uint32_t*)(dl + off) = lo;
                }
            }
        }
    }
}

// ---------------------------------------------------------------------------
// Tensor-core flash attention (unchanged from the passing 1104us version).
// ---------------------------------------------------------------------------
#define AROW  72
#define ATILE (64*AROW*2)     // 9216 B
#define ASMEM (6*ATILE)       // 55296 B

__global__ void __launch_bounds__(128) attn_mma()
{
    extern __shared__ char smbuf[];
    const uint32_t s0  = smem_u32(smbuf);
    const uint32_t sQh = s0,             sQl = s0 + ATILE;
    const uint32_t sKh = s0 + 2*ATILE,   sKl = s0 + 3*ATILE;
    const uint32_t sVh = s0 + 4*ATILE,   sVl = s0 + 5*ATILE;

    const int qt = blockIdx.x, h = blockIdx.y, b = blockIdx.z;
    const int tid = threadIdx.x;
    const int w = tid >> 5, l = tid & 31;

    const size_t head_off = (size_t)(b * HEADS + h) * SEQ * HDIM;
    const __nv_bfloat16* qhp = g_qh + head_off + (size_t)qt * 64 * HDIM;
    const __nv_bfloat16* qlp = g_ql + head_off + (size_t)qt * 64 * HDIM;
    const __nv_bfloat16* khp = g_kh + head_off;
    const __nv_bfloat16* klp = g_kl + head_off;
    const __nv_bfloat16* vhp = g_vh + head_off;
    const __nv_bfloat16* vlp = g_vl + head_off;

    #pragma unroll
    for (int it = 0; it < 4; ++it) {
        const int idx = tid + 128 * it;
        const int row = idx >> 3, seg = idx & 7;
        const uint32_t sp = row * 144 + seg * 16;
        const size_t gp = (size_t)row * HDIM + seg * 8;
        asm volatile("cp.async.cg.shared.global [%0], [%1], 16;"
                     :: "r"(sQh + sp), "l"(qhp + gp) : "memory");
        asm volatile("cp.async.cg.shared.global [%0], [%1], 16;"
                     :: "r"(sQl + sp), "l"(qlp + gp) : "memory");
    }
    auto load_kv = [&](int c) {
        #pragma unroll
        for (int it = 0; it < 4; ++it) {
            const int idx = tid + 128 * it;
            const int row = idx >> 3, seg = idx & 7;
            const uint32_t sp = row * 144 + seg * 16;
            const size_t gp = (size_t)(c * 64 + row) * HDIM + seg * 8;
            asm volatile("cp.async.cg.shared.global [%0], [%1], 16;"
                         :: "r"(sKh + sp), "l"(khp + gp) : "memory");
            asm volatile("cp.async.cg.shared.global [%0], [%1], 16;"
                         :: "r"(sKl + sp), "l"(klp + gp) : "memory");
            asm volatile("cp.async.cg.shared.global [%0], [%1], 16;"
                         :: "r"(sVh + sp), "l"(vhp + gp) : "memory");
            asm volatile("cp.async.cg.shared.global [%0], [%1], 16;"
                         :: "r"(sVl + sp), "l"(vlp + gp) : "memory");
        }
        asm volatile("cp.async.commit_group;" ::: "memory");
    };
    load_kv(0);
    asm volatile("cp.async.wait_group 0;" ::: "memory");
    __syncthreads();

    const int lm = l & 15, lk8 = (l >> 4) * 8;
    uint32_t qfh[4][4], qfl[4][4];
    #pragma unroll
    for (int ks = 0; ks < 4; ++ks) {
        const uint32_t off = (w * 16 + lm) * 144 + ks * 32 + lk8 * 2;
        ldmx4(qfh[ks], sQh + off);
        ldmx4(qfl[ks], sQl + off);
    }

    float m0 = -1e30f, m1 = -1e30f, l0 = 0.f, l1 = 0.f;
    float oacc[8][4];
    #pragma unroll
    for (int t = 0; t < 8; ++t)
        #pragma unroll
        for (int j = 0; j < 4; ++j) oacc[t][j] = 0.f;

    const int koff_t = ((l >> 3) & 1) * 8 + (l & 7);
    const int noff_t = ((l >> 4) & 1) * 8;

    const int nchunk = (qt == 0) ? 1 : 5;
    for (int c = 0; c < nchunk; ++c) {
        if (c > 0) {
            __syncthreads();
            load_kv(c);
            asm volatile("cp.async.wait_group 0;" ::: "memory");
            __syncthreads();
        }

        float sacc[8][4];
        #pragma unroll
        for (int t = 0; t < 8; ++t)
            #pragma unroll
            for (int j = 0; j < 4; ++j) sacc[t][j] = 0.f;

        #pragma unroll
        for (int ks = 0; ks < 4; ++ks) {
            uint32_t kbh[4][4], kbl[4][4];
            #pragma unroll
            for (int nt = 0; nt < 4; ++nt) {
                const uint32_t off = (nt * 16 + lm) * 144 + ks * 32 + lk8 * 2;
                ldmx4(kbh[nt], sKh + off);
                ldmx4(kbl[nt], sKl + off);
            }
            #pragma unroll
            for (int nt = 0; nt < 4; ++nt) {
                mma16816(sacc[2*nt],   qfh[ks], kbh[nt][0], kbh[nt][2]);
                mma16816(sacc[2*nt+1], qfh[ks], kbh[nt][1], kbh[nt][3]);
            }
            #pragma unroll
            for (int nt = 0; nt < 4; ++nt) {
                mma16816(sacc[2*nt],   qfl[ks], kbh[nt][0], kbh[nt][2]);
                mma16816(sacc[2*nt+1], qfl[ks], kbh[nt][1], kbh[nt][3]);
            }
            #pragma unroll
            for (int nt = 0; nt < 4; ++nt) {
                mma16816(sacc[2*nt],   qfh[ks], kbl[nt][0], kbl[nt][2]);
                mma16816(sacc[2*nt+1], qfh[ks], kbl[nt][1], kbl[nt][3]);
            }
        }

        #pragma unroll
        for (int t = 0; t < 8; ++t)
            #pragma unroll
            for (int j = 0; j < 4; ++j) sacc[t][j] *= 0.125f;

        float mx0 = -1e30f, mx1 = -1e30f;
        #pragma unroll
        for (int t = 0; t < 8; ++t) {
            mx0 = fmaxf(mx0, fmaxf(sacc[t][0], sacc[t][1]));
            mx1 = fmaxf(mx1, fmaxf(sacc[t][2], sacc[t][3]));
        }
        mx0 = fmaxf(mx0, __shfl_xor_sync(0xffffffffu, mx0, 1));
        mx0 = fmaxf(mx0, __shfl_xor_sync(0xffffffffu, mx0, 2));
        mx1 = fmaxf(mx1, __shfl_xor_sync(0xffffffffu, mx1, 1));
        mx1 = fmaxf(mx1, __shfl_xor_sync(0xffffffffu, mx1, 2));

        const float mn0 = fmaxf(m0, mx0), mn1 = fmaxf(m1, mx1);
        const float cr0 = __expf(m0 - mn0), cr1 = __expf(m1 - mn1);
        m0 = mn0; m1 = mn1;

        float sm0 = 0.f, sm1 = 0.f;
        #pragma unroll
        for (int t = 0; t < 8; ++t) {
            sacc[t][0] = __expf(sacc[t][0] - mn0);
            sacc[t][1] = __expf(sacc[t][1] - mn0);
            sacc[t][2] = __expf(sacc[t][2] - mn1);
            sacc[t][3] = __expf(sacc[t][3] - mn1);
            sm0 += sacc[t][0] + sacc[t][1];
            sm1 += sacc[t][2] + sacc[t][3];
        }
        sm0 += __shfl_xor_sync(0xffffffffu, sm0, 1);
        sm0 += __shfl_xor_sync(0xffffffffu, sm0, 2);
        sm1 += __shfl_xor_sync(0xffffffffu, sm1, 1);
        sm1 += __shfl_xor_sync(0xffffffffu, sm1, 2);
        l0 = l0 * cr0 + sm0;
        l1 = l1 * cr1 + sm1;

        #pragma unroll
        for (int t = 0; t < 8; ++t) {
            oacc[t][0] *= cr0; oacc[t][1] *= cr0;
            oacc[t][2] *= cr1; oacc[t][3] *= cr1;
        }

        #pragma unroll
        for (int ks = 0; ks < 4; ++ks) {
            uint32_t pah[4], pal[4];
            split2(sacc[2*ks][0],   sacc[2*ks][1],   pah[0], pal[0]);
            split2(sacc[2*ks][2],   sacc[2*ks][3],   pah[1], pal[1]);
            split2(sacc[2*ks+1][0], sacc[2*ks+1][1], pah[2], pal[2]);
            split2(sacc[2*ks+1][2], sacc[2*ks+1][3], pah[3], pal[3]);

            uint32_t vbh[4][4], vbl[4][4];
            #pragma unroll
            for (int nd = 0; nd < 4; ++nd) {
                const uint32_t off = (ks * 16 + koff_t) * 144
                                   + (nd * 16 + noff_t) * 2;
                ldmx4t(vbh[nd], sVh + off);
                ldmx4t(vbl[nd], sVl + off);
            }
            #pragma unroll
            for (int nd = 0; nd < 4; ++nd) {
                mma16816(oacc[2*nd],   pah, vbh[nd][0], vbh[nd][1]);
                mma16816(oacc[2*nd+1], pah, vbh[nd][2], vbh[nd][3]);
            }
            #pragma unroll
            for (int nd = 0; nd < 4; ++nd) {
                mma16816(oacc[2*nd],   pal, vbh[nd][0], vbh[nd][1]);
                mma16816(oacc[2*nd+1], pal, vbh[nd][2], vbh[nd][3]);
            }
            #pragma unroll
            for (int nd = 0; nd < 4; ++nd) {
                mma16816(oacc[2*nd],   pah, vbl[nd][0], vbl[nd][1]);
                mma16816(oacc[2*nd+1], pah, vbl[nd][2], vbl[nd][3]);
            }
        }
    }

    const float inv0 = 1.0f / l0, inv1 = 1.0f / l1;
    const int n0 = qt * 64 + w * 16 + (l >> 2);
    const int n1 = n0 + 8;
    const size_t row0 = ((size_t)b * SEQ + n0) * CH + h * HDIM;
    const size_t row1 = ((size_t)b * SEQ + n1) * CH + h * HDIM;
    #pragma unroll
    for (int t = 0; t < 8; ++t) {
        const int d0 = t * 8 + (l & 3) * 2;
        uint32_t hi, lo;
        split2(oacc[t][0] * inv0, oacc[t][1] * inv0, hi, lo);
        *(uint32_t*)(g_att_hi + row0 + d0) = hi;
        *(uint32_t*)(g_att_lo + row0 + d0) = lo;
        split2(oacc[t][2] * inv1, oacc[t][3] * inv1, hi, lo);
        *(uint32_t*)(g_att_hi + row1 + d0) = hi;
        *(uint32_t*)(g_att_lo + row1 + d0) = lo;
    }
}

// ---------------------------------------------------------------------------
extern "C" void kernel_launch(void* const* d_in, const int* in_sizes, int n_in,
                              void* d_out, int out_size)
{
    const float* x      = (const float*)d_in[0];
    const float* w_qkv  = (const float*)d_in[1];
    const float* b_qkv  = (const float*)d_in[2];
    const float* w_proj = (const float*)d_in[3];
    const float* b_proj = (const float*)d_in[4];
    float* out = (float*)d_out;
    (void)in_sizes; (void)n_in; (void)out_size;

    cudaFuncSetAttribute(gemm_mma<1>, cudaFuncAttributeMaxDynamicSharedMemorySize, SMEM_DYN);
    cudaFuncSetAttribute(gemm_mma<0>, cudaFuncAttributeMaxDynamicSharedMemorySize, SMEM_DYN);
    cudaFuncSetAttribute(attn_mma, cudaFuncAttributeMaxDynamicSharedMemorySize, ASMEM);

    {   // fp32 -> bf16 hi/lo splits
        int n4 = MROWS * KDIM / 4;
        cvt_split<0><<<(n4 + 255) / 256, 256>>>(x, n4);
        n4 = 3 * CH * KDIM / 4;
        cvt_split<1><<<(n4 + 255) / 256, 256>>>(w_qkv, n4);
        n4 = CH * KDIM / 4;
        cvt_split<2><<<(n4 + 255) / 256, 256>>>(w_proj, n4);
    }

    gemm_mma<1><<<dim3(3 * CH / 128, MROWS / 128), 256, SMEM_DYN>>>(b_qkv, nullptr);
    attn_mma<<<dim3(5, HEADS, BATCH), 128, ASMEM>>>();
    gemm_mma<0><<<dim3(CH / 128, MROWS / 128), 256, SMEM_DYN>>>(b_proj, out);
}

// round 17
// speedup vs baseline: 1.0858x; 1.0858x over previous
#include <cuda_runtime.h>
#include <cuda_bf16.h>
#include <cstdint>

#define BATCH 64
#define SEQ   320
#define CH    768
#define HEADS 12
#define HDIM  64
#define KDIM  768
#define MROWS (BATCH*SEQ)   // 20480

// ---------------- device global scratch (allocation-free rule) --------------
__device__ __nv_bfloat16 g_qh[(size_t)BATCH*HEADS*SEQ*HDIM];
__device__ __nv_bfloat16 g_ql[(size_t)BATCH*HEADS*SEQ*HDIM];
__device__ __nv_bfloat16 g_kh[(size_t)BATCH*HEADS*SEQ*HDIM];
__device__ __nv_bfloat16 g_kl[(size_t)BATCH*HEADS*SEQ*HDIM];
__device__ __nv_bfloat16 g_vh[(size_t)BATCH*HEADS*SEQ*HDIM];
__device__ __nv_bfloat16 g_vl[(size_t)BATCH*HEADS*SEQ*HDIM];
__device__ __nv_bfloat16 g_xhi[(size_t)MROWS*KDIM];
__device__ __nv_bfloat16 g_xlo[(size_t)MROWS*KDIM];
__device__ __nv_bfloat16 g_wqkv_hi[(size_t)3*CH*KDIM];
__device__ __nv_bfloat16 g_wqkv_lo[(size_t)3*CH*KDIM];
__device__ __nv_bfloat16 g_wproj_hi[(size_t)CH*KDIM];
__device__ __nv_bfloat16 g_wproj_lo[(size_t)CH*KDIM];
__device__ __nv_bfloat16 g_att_hi[(size_t)MROWS*CH];
__device__ __nv_bfloat16 g_att_lo[(size_t)MROWS*CH];

// ---------------- helpers ---------------------------------------------------
__device__ __forceinline__ uint32_t smem_u32(const void* p) {
    uint32_t a;
    asm("{ .reg .u64 t; cvta.to.shared.u64 t, %1; cvt.u32.u64 %0, t; }"
        : "=r"(a) : "l"(p));
    return a;
}
__device__ __forceinline__ void ldmx4(uint32_t* r, uint32_t addr) {
    asm volatile("ldmatrix.sync.aligned.m8n8.x4.shared.b16 {%0,%1,%2,%3}, [%4];"
        : "=r"(r[0]), "=r"(r[1]), "=r"(r[2]), "=r"(r[3]) : "r"(addr));
}
__device__ __forceinline__ void ldmx4t(uint32_t* r, uint32_t addr) {
    asm volatile("ldmatrix.sync.aligned.m8n8.x4.trans.shared.b16 {%0,%1,%2,%3}, [%4];"
        : "=r"(r[0]), "=r"(r[1]), "=r"(r[2]), "=r"(r[3]) : "r"(addr));
}
__device__ __forceinline__ void mma16816(float* c, const uint32_t* a,
                                         uint32_t b0, uint32_t b1) {
    asm volatile("mma.sync.aligned.m16n8k16.row.col.f32.bf16.bf16.f32 "
        "{%0,%1,%2,%3}, {%4,%5,%6,%7}, {%8,%9}, {%0,%1,%2,%3};"
        : "+f"(c[0]), "+f"(c[1]), "+f"(c[2]), "+f"(c[3])
        : "r"(a[0]), "r"(a[1]), "r"(a[2]), "r"(a[3]), "r"(b0), "r"(b1));
}
__device__ __forceinline__ uint32_t pack_bf2(__nv_bfloat16 a, __nv_bfloat16 b) {
    return ((uint32_t)__bfloat16_as_ushort(b) << 16) | (uint32_t)__bfloat16_as_ushort(a);
}
__device__ __forceinline__ void split2(float x, float y, uint32_t& hi, uint32_t& lo) {
    __nv_bfloat16 hx = __float2bfloat16(x), hy = __float2bfloat16(y);
    hi = pack_bf2(hx, hy);
    lo = pack_bf2(__float2bfloat16(x - __bfloat162float(hx)),
                  __float2bfloat16(y - __bfloat162float(hy)));
}

// ---------------- fp32 -> bf16 hi/lo split ----------------------------------
template<int T>
__global__ void cvt_split(const float* __restrict__ s, int n4) {
    __nv_bfloat16* hi = (T == 0) ? g_xhi : (T == 1) ? g_wqkv_hi : g_wproj_hi;
    __nv_bfloat16* lo = (T == 0) ? g_xlo : (T == 1) ? g_wqkv_lo : g_wproj_lo;
    int i = blockIdx.x * blockDim.x + threadIdx.x;
    if (i >= n4) return;
    float4 v = ((const float4*)s)[i];
    uint32_t h0, l0, h1, l1;
    split2(v.x, v.y, h0, l0);
    split2(v.z, v.w, h1, l1);
    ((uint2*)hi)[i] = make_uint2(h0, h1);
    ((uint2*)lo)[i] = make_uint2(l0, l1);
}

// ---------------------------------------------------------------------------
// bf16-split warp-MMA GEMM. 128x128 CTA tile, FOUR warps (2m x 2n grid),
// warp tile 64x64 — halves ldmatrix traffic per MAC (smem crossbar was the
// binder). BK=32, 2-stage cp.async, one __syncthreads per chunk.
// MODE 1: A=x(split), W=wqkv(split), epilogue splits to bf16 -> g_{q,k,v}{h,l}.
// MODE 0: A=att(split), W=wproj(split), out[m*CH+n] fp32.
// ---------------------------------------------------------------------------
#define RSTRIDE 40
#define TILE_B  (128*RSTRIDE*2)     // 10240 B
#define STAGE_B (4*TILE_B)          // 40960 B
#define SMEM_DYN (2*STAGE_B)        // 81920 B

template<int MODE>
__global__ void __launch_bounds__(128, 2)
gemm_mma(const float* __restrict__ bias, float* __restrict__ out)
{
    extern __shared__ char dsm[];
    __shared__ float sbias[128];

    const __nv_bfloat16* Ahi = (MODE == 1) ? g_xhi : g_att_hi;
    const __nv_bfloat16* Alo = (MODE == 1) ? g_xlo : g_att_lo;
    const __nv_bfloat16* Whi = (MODE == 1) ? g_wqkv_hi : g_wproj_hi;
    const __nv_bfloat16* Wlo = (MODE == 1) ? g_wqkv_lo : g_wproj_lo;

    const int tid = threadIdx.x;
    const int wid = tid >> 5, l = tid & 31;
    const int bx = blockIdx.x, by = blockIdx.y;
    const int warp_m = wid & 1, warp_n = wid >> 1;

    sbias[tid] = bias[bx * 128 + tid];

    const uint32_t sb0 = smem_u32(dsm);
    // loader: 4 tiles x 128 rows x 32 bf16 (4 x 16B segs); 16 cp.async/thread
    const int lrow = tid >> 2, lseg = tid & 3;   // 32 rows per pass, 4 passes
    const __nv_bfloat16* srcs[4] = { Ahi, Alo, Whi, Wlo };
    const int rb_a = by * 128, rb_b = bx * 128;

    auto load_chunk = [&](int c) {
        const uint32_t sb = sb0 + (c & 1) * STAGE_B;
        #pragma unroll
        for (int t = 0; t < 4; ++t) {
            const __nv_bfloat16* src = srcs[t];
            const int rowbase = (t < 2) ? rb_a : rb_b;
            #pragma unroll
            for (int p = 0; p < 4; ++p) {
                const int r = lrow + p * 32;
                const void* gp = src + (size_t)(rowbase + r) * KDIM + c * 32 + lseg * 8;
                uint32_t sp = sb + t * TILE_B + (r * RSTRIDE + lseg * 8) * 2;
                asm volatile("cp.async.cg.shared.global [%0], [%1], 16;"
                             :: "r"(sp), "l"(gp) : "memory");
            }
        }
        asm volatile("cp.async.commit_group;" ::: "memory");
    };

    float acc[4][8][4];
    #pragma unroll
    for (int i = 0; i < 4; i++)
        #pragma unroll
        for (int j = 0; j < 8; j++)
            #pragma unroll
            for (int k = 0; k < 4; k++) acc[i][j][k] = 0.f;

    const int lm = l & 15, lkh = (l >> 4) * 8;
    const uint32_t a_off = ((warp_m * 64 + lm) * RSTRIDE + lkh) * 2;
    const uint32_t b_off = ((warp_n * 64 + lm) * RSTRIDE + lkh) * 2;

    load_chunk(0);

    const int NC = KDIM / 32;   // 24
    for (int c = 0; c < NC; ++c) {
        asm volatile("cp.async.wait_group 0;" ::: "memory");
        __syncthreads();   // publish chunk c; retire prior readers of this buf

        if (c + 1 < NC) load_chunk(c + 1);   // overlaps with compute

        const uint32_t sb = sb0 + (c & 1) * STAGE_B;
        #pragma unroll
        for (int ks = 0; ks < 2; ++ks) {
            const uint32_t koff = ks * 32;
            uint32_t ah[4][4], al[4][4], bb[4][4];
            #pragma unroll
            for (int mf = 0; mf < 4; ++mf) {
                ldmx4(ah[mf], sb + a_off + mf * (16 * RSTRIDE * 2) + koff);
                ldmx4(al[mf], sb + TILE_B + a_off + mf * (16 * RSTRIDE * 2) + koff);
            }
            #pragma unroll
            for (int np = 0; np < 4; ++np)
                ldmx4(bb[np], sb + 2 * TILE_B + b_off + np * (16 * RSTRIDE * 2) + koff);
            // hh
            #pragma unroll
            for (int mf = 0; mf < 4; ++mf)
                #pragma unroll
                for (int np = 0; np < 4; ++np) {
                    mma16816(acc[mf][2*np],   ah[mf], bb[np][0], bb[np][2]);
                    mma16816(acc[mf][2*np+1], ah[mf], bb[np][1], bb[np][3]);
                }
            // lh
            #pragma unroll
            for (int mf = 0; mf < 4; ++mf)
                #pragma unroll
                for (int np = 0; np < 4; ++np) {
                    mma16816(acc[mf][2*np],   al[mf], bb[np][0], bb[np][2]);
                    mma16816(acc[mf][2*np+1], al[mf], bb[np][1], bb[np][3]);
                }
            // hl (Bl reuses bb regs)
            #pragma unroll
            for (int np = 0; np < 4; ++np)
                ldmx4(bb[np], sb + 3 * TILE_B + b_off + np * (16 * RSTRIDE * 2) + koff);
            #pragma unroll
            for (int mf = 0; mf < 4; ++mf)
                #pragma unroll
                for (int np = 0; np < 4; ++np) {
                    mma16816(acc[mf][2*np],   ah[mf], bb[np][0], bb[np][2]);
                    mma16816(acc[mf][2*np+1], ah[mf], bb[np][1], bb[np][3]);
                }
        }
    }

    const int qr = l >> 2, qc = (l & 3) * 2;
    #pragma unroll
    for (int mf = 0; mf < 4; ++mf) {
        #pragma unroll
        for (int nt = 0; nt < 8; ++nt) {
            const int col = warp_n * 64 + nt * 8 + qc;
            const float b0 = sbias[col], b1 = sbias[col + 1];
            #pragma unroll
            for (int half = 0; half < 2; ++half) {
                const int row = warp_m * 64 + mf * 16 + qr + half * 8;
                const float vx = acc[mf][nt][2*half] + b0;
                const float vy = acc[mf][nt][2*half+1] + b1;
                const int m = by * 128 + row;
                if (MODE == 0) {
                    *(float2*)(out + (size_t)m * CH + bx * 128 + col) =
                        make_float2(vx, vy);
                } else {
                    const int cg = bx * 128 + col;
                    const int which = cg / CH;
                    const int rem = cg - which * CH;
                    const int h = rem >> 6, d0 = rem & 63;
                    const int b = m / SEQ, n = m - b * SEQ;
                    __nv_bfloat16* dh = (which == 0) ? g_qh : (which == 1) ? g_kh : g_vh;
                    __nv_bfloat16* dl = (which == 0) ? g_ql : (which == 1) ? g_kl : g_vl;
                    const size_t off = ((size_t)(b * HEADS + h) * SEQ + n) * HDIM + d0;
                    uint32_t hi, lo;
                    split2(vx, vy, hi, lo);
                    *(uint32_t*)(dh + off) = hi;
                    *(uint32_t*)(dl + off) = lo;
                }
            }
        }
    }
}

// ---------------------------------------------------------------------------
// Tensor-core flash attention (byte-identical to the 1104us passing version).
// ---------------------------------------------------------------------------
#define AROW  72
#define ATILE (64*AROW*2)     // 9216 B
#define ASMEM (6*ATILE)       // 55296 B

__global__ void __launch_bounds__(128) attn_mma()
{
    extern __shared__ char smbuf[];
    const uint32_t s0  = smem_u32(smbuf);
    const uint32_t sQh = s0,             sQl = s0 + ATILE;
    const uint32_t sKh = s0 + 2*ATILE,   sKl = s0 + 3*ATILE;
    const uint32_t sVh = s0 + 4*ATILE,   sVl = s0 + 5*ATILE;

    const int qt = blockIdx.x, h = blockIdx.y, b = blockIdx.z;
    const int tid = threadIdx.x;
    const int w = tid >> 5, l = tid & 31;

    const size_t head_off = (size_t)(b * HEADS + h) * SEQ * HDIM;
    const __nv_bfloat16* qhp = g_qh + head_off + (size_t)qt * 64 * HDIM;
    const __nv_bfloat16* qlp = g_ql + head_off + (size_t)qt * 64 * HDIM;
    const __nv_bfloat16* khp = g_kh + head_off;
    const __nv_bfloat16* klp = g_kl + head_off;
    const __nv_bfloat16* vhp = g_vh + head_off;
    const __nv_bfloat16* vlp = g_vl + head_off;

    #pragma unroll
    for (int it = 0; it < 4; ++it) {
        const int idx = tid + 128 * it;
        const int row = idx >> 3, seg = idx & 7;
        const uint32_t sp = row * 144 + seg * 16;
        const size_t gp = (size_t)row * HDIM + seg * 8;
        asm volatile("cp.async.cg.shared.global [%0], [%1], 16;"
                     :: "r"(sQh + sp), "l"(qhp + gp) : "memory");
        asm volatile("cp.async.cg.shared.global [%0], [%1], 16;"
                     :: "r"(sQl + sp), "l"(qlp + gp) : "memory");
    }
    auto load_kv = [&](int c) {
        #pragma unroll
        for (int it = 0; it < 4; ++it) {
            const int idx = tid + 128 * it;
            const int row = idx >> 3, seg = idx & 7;
            const uint32_t sp = row * 144 + seg * 16;
            const size_t gp = (size_t)(c * 64 + row) * HDIM + seg * 8;
            asm volatile("cp.async.cg.shared.global [%0], [%1], 16;"
                         :: "r"(sKh + sp), "l"(khp + gp) : "memory");
            asm volatile("cp.async.cg.shared.global [%0], [%1], 16;"
                         :: "r"(sKl + sp), "l"(klp + gp) : "memory");
            asm volatile("cp.async.cg.shared.global [%0], [%1], 16;"
                         :: "r"(sVh + sp), "l"(vhp + gp) : "memory");
            asm volatile("cp.async.cg.shared.global [%0], [%1], 16;"
                         :: "r"(sVl + sp), "l"(vlp + gp) : "memory");
        }
        asm volatile("cp.async.commit_group;" ::: "memory");
    };
    load_kv(0);
    asm volatile("cp.async.wait_group 0;" ::: "memory");
    __syncthreads();

    const int lm = l & 15, lk8 = (l >> 4) * 8;
    uint32_t qfh[4][4], qfl[4][4];
    #pragma unroll
    for (int ks = 0; ks < 4; ++ks) {
        const uint32_t off = (w * 16 + lm) * 144 + ks * 32 + lk8 * 2;
        ldmx4(qfh[ks], sQh + off);
        ldmx4(qfl[ks], sQl + off);
    }

    float m0 = -1e30f, m1 = -1e30f, l0 = 0.f, l1 = 0.f;
    float oacc[8][4];
    #pragma unroll
    for (int t = 0; t < 8; ++t)
        #pragma unroll
        for (int j = 0; j < 4; ++j) oacc[t][j] = 0.f;

    const int koff_t = ((l >> 3) & 1) * 8 + (l & 7);
    const int noff_t = ((l >> 4) & 1) * 8;

    const int nchunk = (qt == 0) ? 1 : 5;
    for (int c = 0; c < nchunk; ++c) {
        if (c > 0) {
            __syncthreads();
            load_kv(c);
            asm volatile("cp.async.wait_group 0;" ::: "memory");
            __syncthreads();
        }

        float sacc[8][4];
        #pragma unroll
        for (int t = 0; t < 8; ++t)
            #pragma unroll
            for (int j = 0; j < 4; ++j) sacc[t][j] = 0.f;

        #pragma unroll
        for (int ks = 0; ks < 4; ++ks) {
            uint32_t kbh[4][4], kbl[4][4];
            #pragma unroll
            for (int nt = 0; nt < 4; ++nt) {
                const uint32_t off = (nt * 16 + lm) * 144 + ks * 32 + lk8 * 2;
                ldmx4(kbh[nt], sKh + off);
                ldmx4(kbl[nt], sKl + off);
            }
            #pragma unroll
            for (int nt = 0; nt < 4; ++nt) {
                mma16816(sacc[2*nt],   qfh[ks], kbh[nt][0], kbh[nt][2]);
                mma16816(sacc[2*nt+1], qfh[ks], kbh[nt][1], kbh[nt][3]);
            }
            #pragma unroll
            for (int nt = 0; nt < 4; ++nt) {
                mma16816(sacc[2*nt],   qfl[ks], kbh[nt][0], kbh[nt][2]);
                mma16816(sacc[2*nt+1], qfl[ks], kbh[nt][1], kbh[nt][3]);
            }
            #pragma unroll
            for (int nt = 0; nt < 4; ++nt) {
                mma16816(sacc[2*nt],   qfh[ks], kbl[nt][0], kbl[nt][2]);
                mma16816(sacc[2*nt+1], qfh[ks], kbl[nt][1], kbl[nt][3]);
            }
        }

        #pragma unroll
        for (int t = 0; t < 8; ++t)
            #pragma unroll
            for (int j = 0; j < 4; ++j) sacc[t][j] *= 0.125f;

        float mx0 = -1e30f, mx1 = -1e30f;
        #pragma unroll
        for (int t = 0; t < 8; ++t) {
            mx0 = fmaxf(mx0, fmaxf(sacc[t][0], sacc[t][1]));
            mx1 = fmaxf(mx1, fmaxf(sacc[t][2], sacc[t][3]));
        }
        mx0 = fmaxf(mx0, __shfl_xor_sync(0xffffffffu, mx0, 1));
        mx0 = fmaxf(mx0, __shfl_xor_sync(0xffffffffu, mx0, 2));
        mx1 = fmaxf(mx1, __shfl_xor_sync(0xffffffffu, mx1, 1));
        mx1 = fmaxf(mx1, __shfl_xor_sync(0xffffffffu, mx1, 2));

        const float mn0 = fmaxf(m0, mx0), mn1 = fmaxf(m1, mx1);
        const float cr0 = __expf(m0 - mn0), cr1 = __expf(m1 - mn1);
        m0 = mn0; m1 = mn1;

        float sm0 = 0.f, sm1 = 0.f;
        #pragma unroll
        for (int t = 0; t < 8; ++t) {
            sacc[t][0] = __expf(sacc[t][0] - mn0);
            sacc[t][1] = __expf(sacc[t][1] - mn0);
            sacc[t][2] = __expf(sacc[t][2] - mn1);
            sacc[t][3] = __expf(sacc[t][3] - mn1);
            sm0 += sacc[t][0] + sacc[t][1];
            sm1 += sacc[t][2] + sacc[t][3];
        }
        sm0 += __shfl_xor_sync(0xffffffffu, sm0, 1);
        sm0 += __shfl_xor_sync(0xffffffffu, sm0, 2);
        sm1 += __shfl_xor_sync(0xffffffffu, sm1, 1);
        sm1 += __shfl_xor_sync(0xffffffffu, sm1, 2);
        l0 = l0 * cr0 + sm0;
        l1 = l1 * cr1 + sm1;

        #pragma unroll
        for (int t = 0; t < 8; ++t) {
            oacc[t][0] *= cr0; oacc[t][1] *= cr0;
            oacc[t][2] *= cr1; oacc[t][3] *= cr1;
        }

        #pragma unroll
        for (int ks = 0; ks < 4; ++ks) {
            uint32_t pah[4], pal[4];
            split2(sacc[2*ks][0],   sacc[2*ks][1],   pah[0], pal[0]);
            split2(sacc[2*ks][2],   sacc[2*ks][3],   pah[1], pal[1]);
            split2(sacc[2*ks+1][0], sacc[2*ks+1][1], pah[2], pal[2]);
            split2(sacc[2*ks+1][2], sacc[2*ks+1][3], pah[3], pal[3]);

            uint32_t vbh[4][4], vbl[4][4];
            #pragma unroll
            for (int nd = 0; nd < 4; ++nd) {
                const uint32_t off = (ks * 16 + koff_t) * 144
                                   + (nd * 16 + noff_t) * 2;
                ldmx4t(vbh[nd], sVh + off);
                ldmx4t(vbl[nd], sVl + off);
            }
            #pragma unroll
            for (int nd = 0; nd < 4; ++nd) {
                mma16816(oacc[2*nd],   pah, vbh[nd][0], vbh[nd][1]);
                mma16816(oacc[2*nd+1], pah, vbh[nd][2], vbh[nd][3]);
            }
            #pragma unroll
            for (int nd = 0; nd < 4; ++nd) {
                mma16816(oacc[2*nd],   pal, vbh[nd][0], vbh[nd][1]);
                mma16816(oacc[2*nd+1], pal, vbh[nd][2], vbh[nd][3]);
            }
            #pragma unroll
            for (int nd = 0; nd < 4; ++nd) {
                mma16816(oacc[2*nd],   pah, vbl[nd][0], vbl[nd][1]);
                mma16816(oacc[2*nd+1], pah, vbl[nd][2], vbl[nd][3]);
            }
        }
    }

    const float inv0 = 1.0f / l0, inv1 = 1.0f / l1;
    const int n0 = qt * 64 + w * 16 + (l >> 2);
    const int n1 = n0 + 8;
    const size_t row0 = ((size_t)b * SEQ + n0) * CH + h * HDIM;
    const size_t row1 = ((size_t)b * SEQ + n1) * CH + h * HDIM;
    #pragma unroll
    for (int t = 0; t < 8; ++t) {
        const int d0 = t * 8 + (l & 3) * 2;
        uint32_t hi, lo;
        split2(oacc[t][0] * inv0, oacc[t][1] * inv0, hi, lo);
        *(uint32_t*)(g_att_hi + row0 + d0) = hi;
        *(uint32_t*)(g_att_lo + row0 + d0) = lo;
        split2(oacc[t][2] * inv1, oacc[t][3] * inv1, hi, lo);
        *(uint32_t*)(g_att_hi + row1 + d0) = hi;
        *(uint32_t*)(g_att_lo + row1 + d0) = lo;
    }
}

// ---------------------------------------------------------------------------
extern "C" void kernel_launch(void* const* d_in, const int* in_sizes, int n_in,
                              void* d_out, int out_size)
{
    const float* x      = (const float*)d_in[0];
    const float* w_qkv  = (const float*)d_in[1];
    const float* b_qkv  = (const float*)d_in[2];
    const float* w_proj = (const float*)d_in[3];
    const float* b_proj = (const float*)d_in[4];
    float* out = (float*)d_out;
    (void)in_sizes; (void)n_in; (void)out_size;

    cudaFuncSetAttribute(gemm_mma<1>, cudaFuncAttributeMaxDynamicSharedMemorySize, SMEM_DYN);
    cudaFuncSetAttribute(gemm_mma<0>, cudaFuncAttributeMaxDynamicSharedMemorySize, SMEM_DYN);
    cudaFuncSetAttribute(attn_mma, cudaFuncAttributeMaxDynamicSharedMemorySize, ASMEM);

    {   // fp32 -> bf16 hi/lo splits
        int n4 = MROWS * KDIM / 4;
        cvt_split<0><<<(n4 + 255) / 256, 256>>>(x, n4);
        n4 = 3 * CH * KDIM / 4;
        cvt_split<1><<<(n4 + 255) / 256, 256>>>(w_qkv, n4);
        n4 = CH * KDIM / 4;
        cvt_split<2><<<(n4 + 255) / 256, 256>>>(w_proj, n4);
    }

    gemm_mma<1><<<dim3(3 * CH / 128, MROWS / 128), 128, SMEM_DYN>>>(b_qkv, nullptr);
    attn_mma<<<dim3(5, HEADS, BATCH), 128, ASMEM>>>();
    gemm_mma<0><<<dim3(CH / 128, MROWS / 128), 128, SMEM_DYN>>>(b_proj, out);
}